// round 3
// baseline (speedup 1.0000x reference)
#include <cuda_runtime.h>
#include <math.h>

#define FULL 0xFFFFFFFFu

constexpr int D = 32;   // feature dim
constexpr int N = 10;   // sources per group
constexpr int H = 4;    // hidden dim of both tiny MLPs

// One warp per (r,s) group; lane = output dim d (0..31).
__global__ __launch_bounds__(256) void attn2d_kernel(
    const float* __restrict__ q,   const float* __restrict__ k,
    const float* __restrict__ pos, const int*   __restrict__ mask,
    const float* __restrict__ Wq,  const float* __restrict__ Wk,
    const float* __restrict__ Wv,
    const float* __restrict__ pW1, const float* __restrict__ pb1,
    const float* __restrict__ pW2, const float* __restrict__ pb2,
    const float* __restrict__ aW1, const float* __restrict__ ab1,
    const float* __restrict__ aW2, const float* __restrict__ ab2,
    const float* __restrict__ oW,  const float* __restrict__ ob,
    float* __restrict__ out_x,  float* __restrict__ out_attn,
    float* __restrict__ out_std, float* __restrict__ out_nstd,
    int G)
{
    __shared__ float sWq[D * D];
    __shared__ float sOW[D * D];
    const int tid = threadIdx.x;
    for (int i = tid; i < D * D; i += blockDim.x) {
        sWq[i] = Wq[i];
        sOW[i] = oW[i];
    }
    __syncthreads();

    const int lane = tid & 31;

    // ---- per-lane register-resident weights ----
    float wkc[D], wvc[D];                // columns 'lane' of Wk, Wv
#pragma unroll
    for (int j = 0; j < D; j++) {
        wkc[j] = Wk[j * D + lane];
        wvc[j] = Wv[j * D + lane];
    }
    float a1[H], a2[H], p2[H];
#pragma unroll
    for (int c = 0; c < H; c++) {
        a1[c] = aW1[lane * H + c];       // aW1 row 'lane'
        a2[c] = aW2[c * D + lane];       // aW2 column 'lane'
        p2[c] = pW2[c * D + lane];       // pW2 column 'lane'
    }
    float pw1[4][H];
#pragma unroll
    for (int i = 0; i < 4; i++)
#pragma unroll
        for (int c = 0; c < H; c++) pw1[i][c] = pW1[i * H + c];
    float ab1r[H], pb1r[H];
#pragma unroll
    for (int c = 0; c < H; c++) { ab1r[c] = ab1[c]; pb1r[c] = pb1[c]; }
    const float pb2l = pb2[lane];
    const float ab2l = ab2[lane];
    const float obl  = ob[lane];

    const int warpsTotal = (gridDim.x * blockDim.x) >> 5;
    const int warpId = (blockIdx.x * blockDim.x + tid) >> 5;

    for (int g = warpId; g < G; g += warpsTotal) {
        const size_t gND = (size_t)g * (N * D);

        // ---- loads ----
        float qv = q[(size_t)g * D + lane];
        float kv[N];
#pragma unroll
        for (int n = 0; n < N; n++) kv[n] = k[gND + n * D + lane];
        float posA = pos[(size_t)g * (N * 4) + lane];
        float posB = (lane < N * 4 - 32) ? pos[(size_t)g * (N * 4) + 32 + lane] : 0.f;
        int   mv   = (lane < N) ? mask[(size_t)g * N + lane] : 0;

        unsigned vm = __ballot_sync(FULL, (lane < N) && (mv != 0));
        int cnt = __popc(vm);
        if (cnt == 0) { vm = (1u << N) - 1u; cnt = N; }   // torch: all-invalid -> all valid

        // ---- qp = q @ Wq ----
        float qp = 0.f;
#pragma unroll
        for (int j = 0; j < D; j++)
            qp = fmaf(__shfl_sync(FULL, qv, j), sWq[j * D + lane], qp);

        float kpA[N], vpA[N], peA[N], sA[N];

#pragma unroll
        for (int n = 0; n < N; n++) {
            // ---- kp, vp projections (k element broadcast via shfl) ----
            float kp = 0.f, vp = 0.f;
#pragma unroll
            for (int j = 0; j < D; j++) {
                float kj = __shfl_sync(FULL, kv[n], j);
                kp = fmaf(kj, wkc[j], kp);
                vp = fmaf(kj, wvc[j], vp);
            }

            // ---- positional embedding ----
            float posn[4];
#pragma unroll
            for (int i = 0; i < 4; i++) {
                const int idx = n * 4 + i;
                posn[i] = (idx < 32) ? __shfl_sync(FULL, posA, idx)
                                     : __shfl_sync(FULL, posB, idx - 32);
            }
            float pe = pb2l;
#pragma unroll
            for (int c = 0; c < H; c++) {
                float ph = pb1r[c];
#pragma unroll
                for (int i = 0; i < 4; i++) ph = fmaf(posn[i], pw1[i][c], ph);
                ph = fmaxf(ph, 0.f);
                pe = fmaf(ph, p2[c], pe);
            }

            // ---- scores MLP: t = kp - qp + pe; h = t @ aW1 (butterfly over d) ----
            float t = kp - qp + pe;
            float y0 = t * a1[0], y1 = t * a1[1], y2 = t * a1[2], y3 = t * a1[3];
#pragma unroll
            for (int m = 16; m >= 1; m >>= 1) {
                y0 += __shfl_xor_sync(FULL, y0, m);
                y1 += __shfl_xor_sync(FULL, y1, m);
                y2 += __shfl_xor_sync(FULL, y2, m);
                y3 += __shfl_xor_sync(FULL, y3, m);
            }
            float s = ab2l;
            s = fmaf(fmaxf(y0 + ab1r[0], 0.f), a2[0], s);
            s = fmaf(fmaxf(y1 + ab1r[1], 0.f), a2[1], s);
            s = fmaf(fmaxf(y2 + ab1r[2], 0.f), a2[2], s);
            s = fmaf(fmaxf(y3 + ab1r[3], 0.f), a2[3], s);

            kpA[n] = kp; vpA[n] = vp; peA[n] = pe; sA[n] = s;
        }

        // ---- masked softmax over n ----
        float mx = -1e30f;
#pragma unroll
        for (int n = 0; n < N; n++)
            if (vm & (1u << n)) mx = fmaxf(mx, sA[n]);
        float ssum = 0.f;
#pragma unroll
        for (int n = 0; n < N; n++) {
            float e = (vm & (1u << n)) ? __expf(sA[n] - mx) : 0.f;
            sA[n] = e;
            ssum += e;
        }
        const float sinv = 1.f / ssum;

        // ---- masked stats of kp over n (ddof=1) ----
        float mean = 0.f, mabs = 0.f;
#pragma unroll
        for (int n = 0; n < N; n++)
            if (vm & (1u << n)) { mean += kpA[n]; mabs += fabsf(kpA[n]); }
        const float cinv = 1.f / (float)cnt;
        mean *= cinv; mabs *= cinv;
        float var = 0.f;
#pragma unroll
        for (int n = 0; n < N; n++)
            if (vm & (1u << n)) { float dlt = kpA[n] - mean; var = fmaf(dlt, dlt, var); }
        var /= fmaxf((float)(cnt - 1), 1.f);
        float stdv, nstd;
        if (cnt == 1) { stdv = 0.f; nstd = 0.f; }
        else          { stdv = sqrtf(var); nstd = stdv / (mabs + 1e-6f); }

        // ---- weighted sum + attn output ----
        float xv = 0.f;
#pragma unroll
        for (int n = 0; n < N; n++) {
            float a = sA[n] * sinv;
            xv = fmaf(vpA[n] + peA[n], a, xv);
            out_attn[gND + n * D + lane] = a;
        }

        // ---- x = xv @ oW + ob ----
        float xo = obl;
#pragma unroll
        for (int j = 0; j < D; j++)
            xo = fmaf(__shfl_sync(FULL, xv, j), sOW[j * D + lane], xo);

        out_x[(size_t)g * D + lane]    = xo;
        out_std[(size_t)g * D + lane]  = stdv;
        out_nstd[(size_t)g * D + lane] = nstd;
    }
}

extern "C" void kernel_launch(void* const* d_in, const int* in_sizes, int n_in,
                              void* d_out, int out_size)
{
    const float* q    = (const float*)d_in[0];
    const float* k    = (const float*)d_in[1];
    const float* pos  = (const float*)d_in[2];
    const int*   mask = (const int*)  d_in[3];
    const float* Wq   = (const float*)d_in[4];
    const float* Wk   = (const float*)d_in[5];
    const float* Wv   = (const float*)d_in[6];
    const float* pW1  = (const float*)d_in[7];
    const float* pb1  = (const float*)d_in[8];
    const float* pW2  = (const float*)d_in[9];
    const float* pb2  = (const float*)d_in[10];
    const float* aW1  = (const float*)d_in[11];
    const float* ab1  = (const float*)d_in[12];
    const float* aW2  = (const float*)d_in[13];
    const float* ab2  = (const float*)d_in[14];
    const float* oW   = (const float*)d_in[15];
    const float* ob   = (const float*)d_in[16];

    const int G = in_sizes[0] / D;            // R*S groups

    float* out_x    = (float*)d_out;          // [G, D]
    float* out_attn = out_x + (size_t)G * D;  // [G, N, D]
    float* out_std  = out_attn + (size_t)G * N * D;   // [G, D]
    float* out_nstd = out_std + (size_t)G * D;        // [G, D]

    const int threads = 256;
    const int blocks  = 2048;                 // persistent-ish: ~8 groups/warp
    attn2d_kernel<<<blocks, threads>>>(
        q, k, pos, mask, Wq, Wk, Wv,
        pW1, pb1, pW2, pb2, aW1, ab1, aW2, ab2, oW, ob,
        out_x, out_attn, out_std, out_nstd, G);
}

// round 4
// speedup vs baseline: 1.3991x; 1.3991x over previous
#include <cuda_runtime.h>
#include <math.h>

#define FULL 0xFFFFFFFFu
using ull = unsigned long long;

constexpr int D  = 32;   // feature dim
constexpr int N  = 10;   // sources per group
constexpr int H  = 4;    // hidden dim of both tiny MLPs
constexpr int DP = 16;   // dim pairs per group (16 lanes per group, 2 groups/warp)

constexpr ull SGN2 = 0x8000000080000000ULL;
constexpr ull ABS2 = 0x7FFFFFFF7FFFFFFFULL;

// ---- packed f32x2 helpers (sm_103a) ----
__device__ __forceinline__ ull pk2(float lo, float hi) {
    ull r; asm("mov.b64 %0,{%1,%2};" : "=l"(r) : "f"(lo), "f"(hi)); return r;
}
__device__ __forceinline__ ull dup2(float v) {
    ull r; asm("mov.b64 %0,{%1,%1};" : "=l"(r) : "f"(v)); return r;
}
__device__ __forceinline__ void up2(ull p, float& lo, float& hi) {
    asm("mov.b64 {%0,%1},%2;" : "=f"(lo), "=f"(hi) : "l"(p));
}
__device__ __forceinline__ ull fma2(ull a, ull b, ull c) {
    ull r; asm("fma.rn.f32x2 %0,%1,%2,%3;" : "=l"(r) : "l"(a), "l"(b), "l"(c)); return r;
}
__device__ __forceinline__ ull add2(ull a, ull b) {
    ull r; asm("add.rn.f32x2 %0,%1,%2;" : "=l"(r) : "l"(a), "l"(b)); return r;
}
__device__ __forceinline__ ull mul2(ull a, ull b) {
    ull r; asm("mul.rn.f32x2 %0,%1,%2;" : "=l"(r) : "l"(a), "l"(b)); return r;
}

__global__ void __launch_bounds__(256, 2) attn2d_kernel(
    const float* __restrict__ q,   const float* __restrict__ k,
    const float* __restrict__ pos, const int*   __restrict__ mask,
    const float* __restrict__ Wq,  const float* __restrict__ Wk,
    const float* __restrict__ Wv,
    const float* __restrict__ pW1, const float* __restrict__ pb1,
    const float* __restrict__ pW2, const float* __restrict__ pb2,
    const float* __restrict__ aW1, const float* __restrict__ ab1,
    const float* __restrict__ aW2, const float* __restrict__ ab2,
    const float* __restrict__ oW,  const float* __restrict__ ob,
    ull* __restrict__ out_x,  ull* __restrict__ out_attn,
    ull* __restrict__ out_std, ull* __restrict__ out_nstd,
    int G)
{
    // ---- shared: packed weight pairs + per-warp staging ----
    __shared__ __align__(16) ull sWq[D * DP];
    __shared__ __align__(16) ull sWk[D * DP];
    __shared__ __align__(16) ull sWv[D * DP];
    __shared__ __align__(16) ull sOW[D * DP];
    __shared__ __align__(16) ull sK[8][2][N][DP];
    __shared__ __align__(16) ull sQ[8][2][DP];
    __shared__ __align__(16) ull sX[8][2][DP];
    __shared__ __align__(16) ull sPos[8][2][20];

    const int tid = threadIdx.x;
    for (int i = tid; i < D * DP; i += 256) {
        const int j = i >> 4, p2 = (i & 15) * 2;
        sWq[i] = pk2(Wq[j * D + p2], Wq[j * D + p2 + 1]);
        sWk[i] = pk2(Wk[j * D + p2], Wk[j * D + p2 + 1]);
        sWv[i] = pk2(Wv[j * D + p2], Wv[j * D + p2 + 1]);
        sOW[i] = pk2(oW[j * D + p2], oW[j * D + p2 + 1]);
    }
    __syncthreads();

    const int lane = tid & 31, gl = lane & 15, hf = lane >> 4, w = tid >> 5;
    const int d2 = 2 * gl;

    // small per-lane weights (pairs along the dim axis)
    ull a1p[H], a2p[H], p2p[H];
    float ab1r[H];
#pragma unroll
    for (int c = 0; c < H; c++) {
        ab1r[c] = ab1[c];
        a1p[c] = pk2(aW1[d2 * H + c], aW1[(d2 + 1) * H + c]);
        a2p[c] = pk2(aW2[c * D + d2], aW2[c * D + d2 + 1]);
        p2p[c] = pk2(pW2[c * D + d2], pW2[c * D + d2 + 1]);
    }
    const ull pb2p = pk2(pb2[d2], pb2[d2 + 1]);
    const ull ab2p = pk2(ab2[d2], ab2[d2 + 1]);
    const ull obp  = pk2(ob[d2],  ob[d2 + 1]);

    const int warpsTotal = (gridDim.x * blockDim.x) >> 5;
    const int warpG = (blockIdx.x * blockDim.x + tid) >> 5;
    const int GP = (G + 1) >> 1;

    for (int p = warpG; p < GP; p += warpsTotal) {
        int g = 2 * p + hf; if (g >= G) g = G - 1;
        const size_t gDP  = (size_t)g * DP;
        const size_t gNDP = (size_t)g * (N * DP);

        // ---- stage this group's q / k / pos tiles into smem ----
        sQ[w][hf][gl] = ((const ull*)q)[gDP + gl];
#pragma unroll
        for (int n = 0; n < N; n++)
            sK[w][hf][n][gl] = ((const ull*)k)[gNDP + n * DP + gl];
        sPos[w][hf][gl] = ((const ull*)pos)[(size_t)g * 20 + gl];
        if (gl < 4) sPos[w][hf][16 + gl] = ((const ull*)pos)[(size_t)g * 20 + 16 + gl];

        const int mraw = (gl < N) ? mask[(size_t)g * N + gl] : 0;
        const unsigned bal = __ballot_sync(FULL, (gl < N) && (mraw != 0));
        unsigned vm = (bal >> (hf << 4)) & 0x3FFu;
        int cnt = __popc(vm);
        if (cnt == 0) { vm = 0x3FFu; cnt = N; }
        __syncwarp();

        // ---- qp = q @ Wq (pair accumulate, broadcast via LDS) ----
        ull qp = 0;
#pragma unroll
        for (int jj = 0; jj < DP; jj++) {
            float lo, hi; ull tq = sQ[w][hf][jj]; up2(tq, lo, hi);
            qp = fma2(dup2(lo), sWq[(2 * jj) * DP + gl], qp);
            qp = fma2(dup2(hi), sWq[(2 * jj + 1) * DP + gl], qp);
        }
        const ull nqp = qp ^ SGN2;

        // ---- pemb first: sA[n] = pe, vp[n] starts at pe (w = vp+pe is free) ----
        ull sA[N], kp[N], vp[N];
#pragma unroll
        for (int n = 0; n < N; n++) {
            const float4 pv = *(const float4*)&sPos[w][hf][2 * n];
            ull pe = pb2p;
#pragma unroll
            for (int c = 0; c < H; c++) {
                float ph = pb1[c];
                ph = fmaf(pv.x, pW1[0 * H + c], ph);
                ph = fmaf(pv.y, pW1[1 * H + c], ph);
                ph = fmaf(pv.z, pW1[2 * H + c], ph);
                ph = fmaf(pv.w, pW1[3 * H + c], ph);
                ph = fmaxf(ph, 0.f);
                pe = fma2(dup2(ph), p2p[c], pe);
            }
            sA[n] = pe;
            vp[n] = pe;
            kp[n] = 0;
        }

        // ---- kp/vp projections: j-outer, weights hoisted, k broadcast via LDS ----
#pragma unroll
        for (int jj = 0; jj < DP; jj++) {
            const ull wk0 = sWk[(2 * jj) * DP + gl], wk1 = sWk[(2 * jj + 1) * DP + gl];
            const ull wv0 = sWv[(2 * jj) * DP + gl], wv1 = sWv[(2 * jj + 1) * DP + gl];
#pragma unroll
            for (int n = 0; n < N; n++) {
                float lo, hi; ull tk = sK[w][hf][n][jj]; up2(tk, lo, hi);
                const ull dl = dup2(lo), dh = dup2(hi);
                kp[n] = fma2(dl, wk0, kp[n]);
                kp[n] = fma2(dh, wk1, kp[n]);
                vp[n] = fma2(dl, wv0, vp[n]);
                vp[n] = fma2(dh, wv1, vp[n]);
            }
        }

        // ---- scores + online masked stats ----
        ull ksum = 0, kabs = 0, ksq = 0;
#pragma unroll
        for (int n = 0; n < N; n++) {
            const ull t = add2(add2(kp[n], nqp), sA[n]);   // kp - qp + pe
            float y0, y1, y2, y3;
            { float lo, hi; up2(mul2(t, a1p[0]), lo, hi); y0 = lo + hi; }
            { float lo, hi; up2(mul2(t, a1p[1]), lo, hi); y1 = lo + hi; }
            { float lo, hi; up2(mul2(t, a1p[2]), lo, hi); y2 = lo + hi; }
            { float lo, hi; up2(mul2(t, a1p[3]), lo, hi); y3 = lo + hi; }
#pragma unroll
            for (int m = 8; m >= 1; m >>= 1) {
                y0 += __shfl_xor_sync(FULL, y0, m);
                y1 += __shfl_xor_sync(FULL, y1, m);
                y2 += __shfl_xor_sync(FULL, y2, m);
                y3 += __shfl_xor_sync(FULL, y3, m);
            }
            ull s = ab2p;
            s = fma2(dup2(fmaxf(y0 + ab1r[0], 0.f)), a2p[0], s);
            s = fma2(dup2(fmaxf(y1 + ab1r[1], 0.f)), a2p[1], s);
            s = fma2(dup2(fmaxf(y2 + ab1r[2], 0.f)), a2p[2], s);
            s = fma2(dup2(fmaxf(y3 + ab1r[3], 0.f)), a2p[3], s);
            sA[n] = s;

            const float mk = ((vm >> n) & 1u) ? 1.f : 0.f;
            const ull md = dup2(mk);
            const ull kpm = mul2(kp[n], md);
            ksum = add2(ksum, kpm);
            kabs = add2(kabs, kpm & ABS2);
            ksq  = fma2(kpm, kp[n], ksq);
        }

        // ---- masked softmax over n (per dim, pairs) ----
        float mxl = -3e38f, mxh = -3e38f;
#pragma unroll
        for (int n = 0; n < N; n++) {
            float lo, hi; up2(sA[n], lo, hi);
            if ((vm >> n) & 1u) { mxl = fmaxf(mxl, lo); mxh = fmaxf(mxh, hi); }
        }
        float esl = 0.f, esh = 0.f;
#pragma unroll
        for (int n = 0; n < N; n++) {
            float lo, hi; up2(sA[n], lo, hi);
            const bool v = (vm >> n) & 1u;
            const float el = v ? __expf(lo - mxl) : 0.f;
            const float eh = v ? __expf(hi - mxh) : 0.f;
            sA[n] = pk2(el, eh);
            esl += el; esh += eh;
        }
        const ull sinvp = pk2(__fdividef(1.f, esl), __fdividef(1.f, esh));

        // ---- attn out + weighted sum ----
        ull xv = 0;
#pragma unroll
        for (int n = 0; n < N; n++) {
            const ull a = mul2(sA[n], sinvp);
            out_attn[gNDP + n * DP + gl] = a;
            xv = fma2(vp[n], a, xv);
        }

        // ---- stats finale ----
        const float cinv = __fdividef(1.f, (float)cnt);
        const ull meanp = mul2(ksum, dup2(cinv));
        const ull mabsp = mul2(kabs, dup2(cinv));
        const ull cm2 = mul2(mul2(meanp, meanp), dup2((float)cnt));
        ull varp = add2(ksq, cm2 ^ SGN2);                 // sum(m*kp^2) - cnt*mean^2
        const float rdc = __fdividef(1.f, fmaxf((float)(cnt - 1), 1.f));
        varp = mul2(varp, dup2(rdc));
        float vl, vh, mal, mah; up2(varp, vl, vh); up2(mabsp, mal, mah);
        float stl = 0.f, sth = 0.f, nsl = 0.f, nsh = 0.f;
        if (cnt > 1) {
            stl = sqrtf(fmaxf(vl, 0.f)); sth = sqrtf(fmaxf(vh, 0.f));
            nsl = stl / (mal + 1e-6f);   nsh = sth / (mah + 1e-6f);
        }

        // ---- x = xv @ oW + ob ----
        sX[w][hf][gl] = xv;
        __syncwarp();
        ull xo = obp;
#pragma unroll
        for (int jj = 0; jj < DP; jj++) {
            float lo, hi; ull tx = sX[w][hf][jj]; up2(tx, lo, hi);
            xo = fma2(dup2(lo), sOW[(2 * jj) * DP + gl], xo);
            xo = fma2(dup2(hi), sOW[(2 * jj + 1) * DP + gl], xo);
        }
        out_x[gDP + gl]    = xo;
        out_std[gDP + gl]  = pk2(stl, sth);
        out_nstd[gDP + gl] = pk2(nsl, nsh);
        __syncwarp();   // protect staging buffers before next iteration
    }
}

extern "C" void kernel_launch(void* const* d_in, const int* in_sizes, int n_in,
                              void* d_out, int out_size)
{
    const float* q    = (const float*)d_in[0];
    const float* k    = (const float*)d_in[1];
    const float* pos  = (const float*)d_in[2];
    const int*   mask = (const int*)  d_in[3];
    const float* Wq   = (const float*)d_in[4];
    const float* Wk   = (const float*)d_in[5];
    const float* Wv   = (const float*)d_in[6];
    const float* pW1  = (const float*)d_in[7];
    const float* pb1  = (const float*)d_in[8];
    const float* pW2  = (const float*)d_in[9];
    const float* pb2  = (const float*)d_in[10];
    const float* aW1  = (const float*)d_in[11];
    const float* ab1  = (const float*)d_in[12];
    const float* aW2  = (const float*)d_in[13];
    const float* ab2  = (const float*)d_in[14];
    const float* oW   = (const float*)d_in[15];
    const float* ob   = (const float*)d_in[16];

    const int G = in_sizes[0] / D;            // R*S groups

    float* base     = (float*)d_out;
    ull*   out_x    = (ull*)base;                                   // [G, D]
    ull*   out_attn = (ull*)(base + (size_t)G * D);                 // [G, N, D]
    ull*   out_std  = (ull*)(base + (size_t)G * D + (size_t)G * N * D);
    ull*   out_nstd = (ull*)(base + 2 * (size_t)G * D + (size_t)G * N * D);

    const int threads = 256;
    const int blocks  = 304;                  // persistent: 2 blocks/SM on 152 SMs
    attn2d_kernel<<<blocks, threads>>>(
        q, k, pos, mask, Wq, Wk, Wv,
        pW1, pb1, pW2, pb2, aW1, ab1, aW2, ab2, oW, ob,
        out_x, out_attn, out_std, out_nstd, G);
}

// round 6
// speedup vs baseline: 2.1601x; 1.5440x over previous
#include <cuda_runtime.h>
#include <math.h>

#define FULL 0xFFFFFFFFu
using ull = unsigned long long;

constexpr int D  = 32;
constexpr int N  = 10;
constexpr int H  = 4;
constexpr int DP = 16;   // dim-pairs; 16 lanes/group, 2 groups/warp

constexpr ull SGN2 = 0x8000000080000000ULL;
constexpr ull ABS2 = 0x7FFFFFFF7FFFFFFFULL;

__device__ __forceinline__ ull pk2(float lo, float hi) {
    ull r; asm("mov.b64 %0,{%1,%2};" : "=l"(r) : "f"(lo), "f"(hi)); return r;
}
__device__ __forceinline__ ull dup2(float v) {
    ull r; asm("mov.b64 %0,{%1,%1};" : "=l"(r) : "f"(v)); return r;
}
__device__ __forceinline__ void up2(ull p, float& lo, float& hi) {
    asm("mov.b64 {%0,%1},%2;" : "=f"(lo), "=f"(hi) : "l"(p));
}
__device__ __forceinline__ ull fma2(ull a, ull b, ull c) {
    ull r; asm("fma.rn.f32x2 %0,%1,%2,%3;" : "=l"(r) : "l"(a), "l"(b), "l"(c)); return r;
}
__device__ __forceinline__ ull add2(ull a, ull b) {
    ull r; asm("add.rn.f32x2 %0,%1,%2;" : "=l"(r) : "l"(a), "l"(b)); return r;
}
__device__ __forceinline__ ull mul2(ull a, ull b) {
    ull r; asm("mul.rn.f32x2 %0,%1,%2;" : "=l"(r) : "l"(a), "l"(b)); return r;
}

__global__ void __launch_bounds__(256, 2) attn2d_kernel(
    const float* __restrict__ q,   const float* __restrict__ k,
    const float* __restrict__ pos, const int*   __restrict__ mask,
    const float* __restrict__ Wq,  const float* __restrict__ Wk,
    const float* __restrict__ Wv,
    const float* __restrict__ pW1, const float* __restrict__ pb1,
    const float* __restrict__ pW2, const float* __restrict__ pb2,
    const float* __restrict__ aW1, const float* __restrict__ ab1,
    const float* __restrict__ aW2, const float* __restrict__ ab2,
    const float* __restrict__ oW,  const float* __restrict__ ob,
    ull* __restrict__ out_x,  ull* __restrict__ out_attn,
    ull* __restrict__ out_std, ull* __restrict__ out_nstd,
    int G)
{
    // ---- weights: row-pair interleaved ull2 -> one LDS.128 = 2 rows ----
    __shared__ __align__(16) ulonglong2 sWqP[16][16];
    __shared__ __align__(16) ulonglong2 sWkP[16][16];
    __shared__ __align__(16) ulonglong2 sWvP[16][16];
    __shared__ __align__(16) ulonglong2 sOWP[16][16];
    // ---- per-warp staging (ull2 = 4 floats) ----
    // k group-pair = 640 floats = 160 ull2; group = 80 ull2; source n = 8 ull2
    __shared__ __align__(16) ulonglong2 sK2[8][160];  // [hf*80 + n*8 + j4]
    __shared__ __align__(16) ulonglong2 sQ2[8][16];   // [hf*8 + jq]
    __shared__ __align__(16) ulonglong2 sX2[8][16];
    __shared__ __align__(16) ulonglong2 sP2[8][20];   // [hf*10 + n]

    const int tid = threadIdx.x;
    {   // one item per thread: (j2, gl)
        const int j2 = tid >> 4, gl2 = (tid & 15) * 2;
        ulonglong2 t;
        t.x = pk2(Wq[(2*j2)*D + gl2],   Wq[(2*j2)*D + gl2+1]);
        t.y = pk2(Wq[(2*j2+1)*D + gl2], Wq[(2*j2+1)*D + gl2+1]);
        sWqP[j2][tid & 15] = t;
        t.x = pk2(Wk[(2*j2)*D + gl2],   Wk[(2*j2)*D + gl2+1]);
        t.y = pk2(Wk[(2*j2+1)*D + gl2], Wk[(2*j2+1)*D + gl2+1]);
        sWkP[j2][tid & 15] = t;
        t.x = pk2(Wv[(2*j2)*D + gl2],   Wv[(2*j2)*D + gl2+1]);
        t.y = pk2(Wv[(2*j2+1)*D + gl2], Wv[(2*j2+1)*D + gl2+1]);
        sWvP[j2][tid & 15] = t;
        t.x = pk2(oW[(2*j2)*D + gl2],   oW[(2*j2)*D + gl2+1]);
        t.y = pk2(oW[(2*j2+1)*D + gl2], oW[(2*j2+1)*D + gl2+1]);
        sOWP[j2][tid & 15] = t;
    }
    __syncthreads();

    const int lane = tid & 31, gl = lane & 15, hf = lane >> 4, w = tid >> 5;
    const int d2 = 2 * gl;

    ull a1p[H], a2p[H], p2p[H];
    float ab1r[H];
#pragma unroll
    for (int c = 0; c < H; c++) {
        ab1r[c] = ab1[c];
        a1p[c] = pk2(aW1[d2 * H + c], aW1[(d2 + 1) * H + c]);
        a2p[c] = pk2(aW2[c * D + d2], aW2[c * D + d2 + 1]);
        p2p[c] = pk2(pW2[c * D + d2], pW2[c * D + d2 + 1]);
    }
    const ull pb2p = pk2(pb2[d2], pb2[d2 + 1]);
    const ull ab2p = pk2(ab2[d2], ab2[d2 + 1]);
    const ull obp  = pk2(ob[d2],  ob[d2 + 1]);

    const int warpsTotal = (gridDim.x * blockDim.x) >> 5;
    const int warpG = (blockIdx.x * blockDim.x + tid) >> 5;
    const int GP = G >> 1;                       // G even (R*S)

    for (int p = warpG; p < GP; p += warpsTotal) {
        const int g = 2 * p + hf;
        const size_t gDP  = (size_t)g * DP;
        const size_t gNDP = (size_t)g * (N * DP);

        // ---- flat vectorized staging (group pair contiguous in gmem) ----
        {
            const ulonglong2* kf = (const ulonglong2*)k + (size_t)p * 160;
#pragma unroll
            for (int i = 0; i < 5; i++)
                sK2[w][i * 32 + lane] = kf[i * 32 + lane];
            if (lane < 16)
                sQ2[w][lane] = ((const ulonglong2*)q)[(size_t)p * 16 + lane];
            if (lane < 20)
                sP2[w][lane] = ((const ulonglong2*)pos)[(size_t)p * 20 + lane];
        }
        const int mraw = (lane < 20) ? mask[(size_t)p * 20 + lane] : 0;
        const unsigned bal = __ballot_sync(FULL, (lane < 20) && (mraw != 0));
        unsigned vm = (bal >> (hf * 10)) & 0x3FFu;
        int cnt = __popc(vm);
        if (cnt == 0) { vm = 0x3FFu; cnt = N; }
        __syncwarp();

        // ---- qp = q @ Wq ----
        ull qp = 0;
#pragma unroll
        for (int jq = 0; jq < 8; jq++) {
            const ulonglong2 q4 = sQ2[w][hf * 8 + jq];
            float q0, q1, q2, q3; up2(q4.x, q0, q1); up2(q4.y, q2, q3);
            const ulonglong2 w01 = sWqP[2 * jq][gl];
            const ulonglong2 w23 = sWqP[2 * jq + 1][gl];
            qp = fma2(dup2(q0), w01.x, qp);
            qp = fma2(dup2(q1), w01.y, qp);
            qp = fma2(dup2(q2), w23.x, qp);
            qp = fma2(dup2(q3), w23.y, qp);
        }
        const ull nqp = qp ^ SGN2;

        // ---- pemb: sA[n] = pe, vp[n] starts at pe ----
        ull sA[N], kp[N], vp[N];
#pragma unroll
        for (int n = 0; n < N; n++) {
            const ulonglong2 pp = sP2[w][hf * 10 + n];
            float px, py, pz, pw; up2(pp.x, px, py); up2(pp.y, pz, pw);
            ull pe = pb2p;
#pragma unroll
            for (int c = 0; c < H; c++) {
                float ph = pb1[c];
                ph = fmaf(px, pW1[0 * H + c], ph);
                ph = fmaf(py, pW1[1 * H + c], ph);
                ph = fmaf(pz, pW1[2 * H + c], ph);
                ph = fmaf(pw, pW1[3 * H + c], ph);
                ph = fmaxf(ph, 0.f);
                pe = fma2(dup2(ph), p2p[c], pe);
            }
            sA[n] = pe;
            vp[n] = pe;
            kp[n] = 0;
        }

        // ---- kp/vp projections: 4 j-rows per step, LDS.128 k + weights ----
#pragma unroll
        for (int j4 = 0; j4 < 8; j4++) {
            const ulonglong2 wk01 = sWkP[2 * j4][gl];
            const ulonglong2 wk23 = sWkP[2 * j4 + 1][gl];
            const ulonglong2 wv01 = sWvP[2 * j4][gl];
            const ulonglong2 wv23 = sWvP[2 * j4 + 1][gl];
#pragma unroll
            for (int n = 0; n < N; n++) {
                const ulonglong2 kk = sK2[w][hf * 80 + n * 8 + j4];
                float k0, k1, k2, k3; up2(kk.x, k0, k1); up2(kk.y, k2, k3);
                const ull d0 = dup2(k0), d1 = dup2(k1), d2d = dup2(k2), d3 = dup2(k3);
                kp[n] = fma2(d0, wk01.x, kp[n]);
                kp[n] = fma2(d1, wk01.y, kp[n]);
                kp[n] = fma2(d2d, wk23.x, kp[n]);
                kp[n] = fma2(d3, wk23.y, kp[n]);
                vp[n] = fma2(d0, wv01.x, vp[n]);
                vp[n] = fma2(d1, wv01.y, vp[n]);
                vp[n] = fma2(d2d, wv23.x, vp[n]);
                vp[n] = fma2(d3, wv23.y, vp[n]);
            }
        }

        // ---- scores (butterfly) + online masked stats ----
        ull ksum = 0, kabs = 0, ksq = 0;
#pragma unroll
        for (int n = 0; n < N; n++) {
            const ull t = add2(add2(kp[n], nqp), sA[n]);   // kp - qp + pe
            float y0, y1, y2, y3;
            { float lo, hi; up2(mul2(t, a1p[0]), lo, hi); y0 = lo + hi; }
            { float lo, hi; up2(mul2(t, a1p[1]), lo, hi); y1 = lo + hi; }
            { float lo, hi; up2(mul2(t, a1p[2]), lo, hi); y2 = lo + hi; }
            { float lo, hi; up2(mul2(t, a1p[3]), lo, hi); y3 = lo + hi; }
#pragma unroll
            for (int m = 8; m >= 1; m >>= 1) {
                y0 += __shfl_xor_sync(FULL, y0, m);
                y1 += __shfl_xor_sync(FULL, y1, m);
                y2 += __shfl_xor_sync(FULL, y2, m);
                y3 += __shfl_xor_sync(FULL, y3, m);
            }
            ull s = ab2p;
            s = fma2(dup2(fmaxf(y0 + ab1r[0], 0.f)), a2p[0], s);
            s = fma2(dup2(fmaxf(y1 + ab1r[1], 0.f)), a2p[1], s);
            s = fma2(dup2(fmaxf(y2 + ab1r[2], 0.f)), a2p[2], s);
            s = fma2(dup2(fmaxf(y3 + ab1r[3], 0.f)), a2p[3], s);
            sA[n] = s;

            const float mk = ((vm >> n) & 1u) ? 1.f : 0.f;
            const ull md = dup2(mk);
            const ull kpm = mul2(kp[n], md);
            ksum = add2(ksum, kpm);
            kabs = add2(kabs, kpm & ABS2);
            ksq  = fma2(kpm, kp[n], ksq);
        }

        // ---- masked softmax over n ----
        float mxl = -3e38f, mxh = -3e38f;
#pragma unroll
        for (int n = 0; n < N; n++) {
            float lo, hi; up2(sA[n], lo, hi);
            if ((vm >> n) & 1u) { mxl = fmaxf(mxl, lo); mxh = fmaxf(mxh, hi); }
        }
        float esl = 0.f, esh = 0.f;
#pragma unroll
        for (int n = 0; n < N; n++) {
            float lo, hi; up2(sA[n], lo, hi);
            const bool v = (vm >> n) & 1u;
            const float el = v ? __expf(lo - mxl) : 0.f;
            const float eh = v ? __expf(hi - mxh) : 0.f;
            sA[n] = pk2(el, eh);
            esl += el; esh += eh;
        }
        const ull sinvp = pk2(__fdividef(1.f, esl), __fdividef(1.f, esh));

        // ---- attn out + weighted sum ----
        ull xv = 0;
#pragma unroll
        for (int n = 0; n < N; n++) {
            const ull a = mul2(sA[n], sinvp);
            out_attn[gNDP + n * DP + gl] = a;
            xv = fma2(vp[n], a, xv);
        }

        // ---- stats finale ----
        const float cinv = __fdividef(1.f, (float)cnt);
        const ull meanp = mul2(ksum, dup2(cinv));
        const ull mabsp = mul2(kabs, dup2(cinv));
        const ull cm2 = mul2(mul2(meanp, meanp), dup2((float)cnt));
        ull varp = add2(ksq, cm2 ^ SGN2);
        const float rdc = __fdividef(1.f, fmaxf((float)(cnt - 1), 1.f));
        varp = mul2(varp, dup2(rdc));
        float vl, vh, mal, mah; up2(varp, vl, vh); up2(mabsp, mal, mah);
        float stl = 0.f, sth = 0.f, nsl = 0.f, nsh = 0.f;
        if (cnt > 1) {
            stl = sqrtf(fmaxf(vl, 0.f)); sth = sqrtf(fmaxf(vh, 0.f));
            nsl = stl / (mal + 1e-6f);   nsh = sth / (mah + 1e-6f);
        }

        // ---- x = xv @ oW + ob ----
        ((ull*)sX2[w])[hf * DP + gl] = xv;
        __syncwarp();
        ull xo = obp;
#pragma unroll
        for (int jx = 0; jx < 8; jx++) {
            const ulonglong2 x4 = sX2[w][hf * 8 + jx];
            float x0, x1, x2, x3; up2(x4.x, x0, x1); up2(x4.y, x2, x3);
            const ulonglong2 w01 = sOWP[2 * jx][gl];
            const ulonglong2 w23 = sOWP[2 * jx + 1][gl];
            xo = fma2(dup2(x0), w01.x, xo);
            xo = fma2(dup2(x1), w01.y, xo);
            xo = fma2(dup2(x2), w23.x, xo);
            xo = fma2(dup2(x3), w23.y, xo);
        }
        out_x[gDP + gl]    = xo;
        out_std[gDP + gl]  = pk2(stl, sth);
        out_nstd[gDP + gl] = pk2(nsl, nsh);
        __syncwarp();   // protect staging before next iteration
    }
}

extern "C" void kernel_launch(void* const* d_in, const int* in_sizes, int n_in,
                              void* d_out, int out_size)
{
    const float* q    = (const float*)d_in[0];
    const float* k    = (const float*)d_in[1];
    const float* pos  = (const float*)d_in[2];
    const int*   mask = (const int*)  d_in[3];
    const float* Wq   = (const float*)d_in[4];
    const float* Wk   = (const float*)d_in[5];
    const float* Wv   = (const float*)d_in[6];
    const float* pW1  = (const float*)d_in[7];
    const float* pb1  = (const float*)d_in[8];
    const float* pW2  = (const float*)d_in[9];
    const float* pb2  = (const float*)d_in[10];
    const float* aW1  = (const float*)d_in[11];
    const float* ab1  = (const float*)d_in[12];
    const float* aW2  = (const float*)d_in[13];
    const float* ab2  = (const float*)d_in[14];
    const float* oW   = (const float*)d_in[15];
    const float* ob   = (const float*)d_in[16];

    const int G = in_sizes[0] / D;

    float* base     = (float*)d_out;
    ull*   out_x    = (ull*)base;
    ull*   out_attn = (ull*)(base + (size_t)G * D);
    ull*   out_std  = (ull*)(base + (size_t)G * D + (size_t)G * N * D);
    ull*   out_nstd = (ull*)(base + 2 * (size_t)G * D + (size_t)G * N * D);

    const int threads = 256;
    const int blocks  = 304;
    attn2d_kernel<<<blocks, threads>>>(
        q, k, pos, mask, Wq, Wk, Wv,
        pW1, pb1, pW2, pb2, aW1, ab1, aW2, ab2, oW, ob,
        out_x, out_attn, out_std, out_nstd, G);
}

// round 7
// speedup vs baseline: 2.3459x; 1.0860x over previous
#include <cuda_runtime.h>
#include <math.h>

#define FULL 0xFFFFFFFFu
using ull = unsigned long long;

constexpr int D  = 32;
constexpr int N  = 10;
constexpr int H  = 4;
constexpr int DP = 16;   // dim-pairs; 16 lanes/group, 2 groups/warp

constexpr ull SGN2 = 0x8000000080000000ULL;
constexpr ull ABS2 = 0x7FFFFFFF7FFFFFFFULL;

__device__ __forceinline__ ull pk2(float lo, float hi) {
    ull r; asm("mov.b64 %0,{%1,%2};" : "=l"(r) : "f"(lo), "f"(hi)); return r;
}
__device__ __forceinline__ ull dup2(float v) {
    ull r; asm("mov.b64 %0,{%1,%1};" : "=l"(r) : "f"(v)); return r;
}
__device__ __forceinline__ void up2(ull p, float& lo, float& hi) {
    asm("mov.b64 {%0,%1},%2;" : "=f"(lo), "=f"(hi) : "l"(p));
}
__device__ __forceinline__ ull fma2(ull a, ull b, ull c) {
    ull r; asm("fma.rn.f32x2 %0,%1,%2,%3;" : "=l"(r) : "l"(a), "l"(b), "l"(c)); return r;
}
__device__ __forceinline__ ull add2(ull a, ull b) {
    ull r; asm("add.rn.f32x2 %0,%1,%2;" : "=l"(r) : "l"(a), "l"(b)); return r;
}
__device__ __forceinline__ ull mul2(ull a, ull b) {
    ull r; asm("mul.rn.f32x2 %0,%1,%2;" : "=l"(r) : "l"(a), "l"(b)); return r;
}

__global__ void __launch_bounds__(256, 2) attn2d_kernel(
    const float* __restrict__ q,   const float* __restrict__ k,
    const float* __restrict__ pos, const int*   __restrict__ mask,
    const float* __restrict__ Wq,  const float* __restrict__ Wk,
    const float* __restrict__ Wv,
    const float* __restrict__ pW1, const float* __restrict__ pb1,
    const float* __restrict__ pW2, const float* __restrict__ pb2,
    const float* __restrict__ aW1, const float* __restrict__ ab1,
    const float* __restrict__ aW2, const float* __restrict__ ab2,
    const float* __restrict__ oW,  const float* __restrict__ ob,
    ull* __restrict__ out_x,  ull* __restrict__ out_attn,
    ull* __restrict__ out_std, ull* __restrict__ out_nstd,
    int G)
{
    // ---- weights: row-pair interleaved ull2 -> one LDS.128 = 2 rows ----
    __shared__ __align__(16) ulonglong2 sWqP[16][16];
    __shared__ __align__(16) ulonglong2 sWkP[16][16];
    __shared__ __align__(16) ulonglong2 sWvP[16][16];
    __shared__ __align__(16) ulonglong2 sOWP[16][16];
    __shared__ __align__(16) ulonglong2 sA1[4][8];   // aW1 column c, dim-pair packed
    // ---- per-warp staging, UNIONED regions (sequential lifetimes) ----
    // regA: phase1 = k tile (160 ull2 = group-pair), phase2 = t rows [20][8] ull2 (swizzled)
    // regB: phase1 = pos (20 ull2),                 phase2 = y [80] floats
    __shared__ __align__(16) ulonglong2 sRegA[8][160];
    __shared__ __align__(16) ulonglong2 sRegB[8][20];
    __shared__ __align__(16) ulonglong2 sQ2[8][16];
    __shared__ __align__(16) ulonglong2 sX2[8][16];

    const int tid = threadIdx.x;
    {   // weight staging: one item per thread (j2, gl)
        const int j2 = tid >> 4, gl2 = (tid & 15) * 2;
        ulonglong2 t;
        t.x = pk2(Wq[(2*j2)*D + gl2],   Wq[(2*j2)*D + gl2+1]);
        t.y = pk2(Wq[(2*j2+1)*D + gl2], Wq[(2*j2+1)*D + gl2+1]);
        sWqP[j2][tid & 15] = t;
        t.x = pk2(Wk[(2*j2)*D + gl2],   Wk[(2*j2)*D + gl2+1]);
        t.y = pk2(Wk[(2*j2+1)*D + gl2], Wk[(2*j2+1)*D + gl2+1]);
        sWkP[j2][tid & 15] = t;
        t.x = pk2(Wv[(2*j2)*D + gl2],   Wv[(2*j2)*D + gl2+1]);
        t.y = pk2(Wv[(2*j2+1)*D + gl2], Wv[(2*j2+1)*D + gl2+1]);
        sWvP[j2][tid & 15] = t;
        t.x = pk2(oW[(2*j2)*D + gl2],   oW[(2*j2)*D + gl2+1]);
        t.y = pk2(oW[(2*j2+1)*D + gl2], oW[(2*j2+1)*D + gl2+1]);
        sOWP[j2][tid & 15] = t;
    }
    if (tid < 32) {   // aW1 columns: (c, jj) packed by dim pairs
        const int c = tid >> 3, jj = tid & 7;
        ulonglong2 t;
        t.x = pk2(aW1[(4*jj+0)*H + c], aW1[(4*jj+1)*H + c]);
        t.y = pk2(aW1[(4*jj+2)*H + c], aW1[(4*jj+3)*H + c]);
        sA1[c][jj] = t;
    }
    __syncthreads();

    const int lane = tid & 31, gl = lane & 15, hf = lane >> 4, w = tid >> 5;
    const int d2 = 2 * gl;
    const int cML = lane & 3;               // fixed score-MLP column per lane
    const float ab1c = ab1[cML];

    ull a2p[H], p2p[H];
#pragma unroll
    for (int c = 0; c < H; c++) {
        a2p[c] = pk2(aW2[c * D + d2], aW2[c * D + d2 + 1]);
        p2p[c] = pk2(pW2[c * D + d2], pW2[c * D + d2 + 1]);
    }
    const ull pb2p = pk2(pb2[d2], pb2[d2 + 1]);
    const ull ab2p = pk2(ab2[d2], ab2[d2 + 1]);
    const ull obp  = pk2(ob[d2],  ob[d2 + 1]);

    ull* const  sTu = (ull*)sRegA[w];       // t rows: [row][16 ull], XOR-swizzled
    float* const sY = (float*)sRegB[w];     // y: 80 floats

    const int warpsTotal = (gridDim.x * blockDim.x) >> 5;
    const int warpG = (blockIdx.x * blockDim.x + tid) >> 5;
    const int GP = G >> 1;                  // G even (R*S)

    for (int p = warpG; p < GP; p += warpsTotal) {
        const int g = 2 * p + hf;
        const size_t gDP  = (size_t)g * DP;
        const size_t gNDP = (size_t)g * (N * DP);

        // ---- flat vectorized staging (group pair contiguous in gmem) ----
        {
            const ulonglong2* kf = (const ulonglong2*)k + (size_t)p * 160;
#pragma unroll
            for (int i = 0; i < 5; i++)
                sRegA[w][i * 32 + lane] = kf[i * 32 + lane];
            if (lane < 16)
                sQ2[w][lane] = ((const ulonglong2*)q)[(size_t)p * 16 + lane];
            if (lane < 20)
                sRegB[w][lane] = ((const ulonglong2*)pos)[(size_t)p * 20 + lane];
        }
        const int mraw = (lane < 20) ? mask[(size_t)p * 20 + lane] : 0;
        const unsigned bal = __ballot_sync(FULL, (lane < 20) && (mraw != 0));
        unsigned vm = (bal >> (hf * 10)) & 0x3FFu;
        int cnt = __popc(vm);
        if (cnt == 0) { vm = 0x3FFu; cnt = N; }
        __syncwarp();

        // ---- qp = q @ Wq ----
        ull qp = 0;
#pragma unroll
        for (int jq = 0; jq < 8; jq++) {
            const ulonglong2 q4 = sQ2[w][hf * 8 + jq];
            float q0, q1, q2, q3; up2(q4.x, q0, q1); up2(q4.y, q2, q3);
            const ulonglong2 w01 = sWqP[2 * jq][gl];
            const ulonglong2 w23 = sWqP[2 * jq + 1][gl];
            qp = fma2(dup2(q0), w01.x, qp);
            qp = fma2(dup2(q1), w01.y, qp);
            qp = fma2(dup2(q2), w23.x, qp);
            qp = fma2(dup2(q3), w23.y, qp);
        }
        const ull nqp = qp ^ SGN2;

        // ---- pemb: pe[n]; vp[n] starts at pe ----
        ull pe[N], kp[N], vp[N];
#pragma unroll
        for (int n = 0; n < N; n++) {
            const ulonglong2 pp = sRegB[w][hf * 10 + n];
            float px, py, pz, pw; up2(pp.x, px, py); up2(pp.y, pz, pw);
            ull pv = pb2p;
#pragma unroll
            for (int c = 0; c < H; c++) {
                float ph = pb1[c];
                ph = fmaf(px, pW1[0 * H + c], ph);
                ph = fmaf(py, pW1[1 * H + c], ph);
                ph = fmaf(pz, pW1[2 * H + c], ph);
                ph = fmaf(pw, pW1[3 * H + c], ph);
                ph = fmaxf(ph, 0.f);
                pv = fma2(dup2(ph), p2p[c], pv);
            }
            pe[n] = pv;
            vp[n] = pv;
            kp[n] = 0;
        }

        // ---- kp/vp projections: 4 j-rows per step, LDS.128 k + weights ----
#pragma unroll
        for (int j4 = 0; j4 < 8; j4++) {
            const ulonglong2 wk01 = sWkP[2 * j4][gl];
            const ulonglong2 wk23 = sWkP[2 * j4 + 1][gl];
            const ulonglong2 wv01 = sWvP[2 * j4][gl];
            const ulonglong2 wv23 = sWvP[2 * j4 + 1][gl];
#pragma unroll
            for (int n = 0; n < N; n++) {
                const ulonglong2 kk = sRegA[w][hf * 80 + n * 8 + j4];
                float k0, k1, k2, k3; up2(kk.x, k0, k1); up2(kk.y, k2, k3);
                const ull d0 = dup2(k0), d1 = dup2(k1), d2d = dup2(k2), d3 = dup2(k3);
                kp[n] = fma2(d0, wk01.x, kp[n]);
                kp[n] = fma2(d1, wk01.y, kp[n]);
                kp[n] = fma2(d2d, wk23.x, kp[n]);
                kp[n] = fma2(d3, wk23.y, kp[n]);
                vp[n] = fma2(d0, wv01.x, vp[n]);
                vp[n] = fma2(d1, wv01.y, vp[n]);
                vp[n] = fma2(d2d, wv23.x, vp[n]);
                vp[n] = fma2(d3, wv23.y, vp[n]);
            }
        }
        __syncwarp();   // all sRegA (k) reads done before t overwrites it

        // ---- t = kp - qp + pe -> smem (swizzled); online masked stats ----
        ull ksum = 0, kabs = 0, ksq = 0;
#pragma unroll
        for (int n = 0; n < N; n++) {
            const int row = hf * 10 + n;
            sTu[row * 16 + (gl ^ ((row & 7) << 1))] = add2(add2(kp[n], nqp), pe[n]);
            const float mk = ((vm >> n) & 1u) ? 1.f : 0.f;
            const ull md = dup2(mk);
            const ull kpm = mul2(kp[n], md);
            ksum = add2(ksum, kpm);
            kabs = add2(kabs, kpm & ABS2);
            ksq  = fma2(kpm, kp[n], ksq);
        }
        __syncwarp();

        // ---- 80 dot-product tasks: y[grp][n][c] = relu(t . aW1[:,c] + ab1[c]) ----
        {
            const ulonglong2* sT2 = (const ulonglong2*)sTu;
#pragma unroll
            for (int r = 0; r < 2; r++) {
                const int t_id = r * 32 + lane;
                const int row = t_id >> 2;       // grp*10 + n
                const int sw = row & 7;
                ull acc = 0;
#pragma unroll
                for (int jj = 0; jj < 8; jj++) {
                    const ulonglong2 tt = sT2[row * 8 + (jj ^ sw)];
                    const ulonglong2 ww = sA1[cML][jj];
                    acc = fma2(tt.x, ww.x, acc);
                    acc = fma2(tt.y, ww.y, acc);
                }
                float lo, hi; up2(acc, lo, hi);
                sY[t_id] = fmaxf(lo + hi + ab1c, 0.f);
            }
            if (lane < 16) {
                const int t_id = 64 + lane;
                const int row = t_id >> 2;
                const int sw = row & 7;
                ull acc = 0;
#pragma unroll
                for (int jj = 0; jj < 8; jj++) {
                    const ulonglong2 tt = sT2[row * 8 + (jj ^ sw)];
                    const ulonglong2 ww = sA1[cML][jj];
                    acc = fma2(tt.x, ww.x, acc);
                    acc = fma2(tt.y, ww.y, acc);
                }
                float lo, hi; up2(acc, lo, hi);
                sY[t_id] = fmaxf(lo + hi + ab1c, 0.f);
            }
        }
        __syncwarp();

        // ---- scores from y; masked softmax over n ----
        ull sA[N];
#pragma unroll
        for (int n = 0; n < N; n++) {
            const float4 y4 = *(const float4*)&sY[(hf * 10 + n) * 4];
            ull s = ab2p;
            s = fma2(dup2(y4.x), a2p[0], s);
            s = fma2(dup2(y4.y), a2p[1], s);
            s = fma2(dup2(y4.z), a2p[2], s);
            s = fma2(dup2(y4.w), a2p[3], s);
            sA[n] = s;
        }
        float mxl = -3e38f, mxh = -3e38f;
#pragma unroll
        for (int n = 0; n < N; n++) {
            float lo, hi; up2(sA[n], lo, hi);
            if ((vm >> n) & 1u) { mxl = fmaxf(mxl, lo); mxh = fmaxf(mxh, hi); }
        }
        float esl = 0.f, esh = 0.f;
#pragma unroll
        for (int n = 0; n < N; n++) {
            float lo, hi; up2(sA[n], lo, hi);
            const bool v = (vm >> n) & 1u;
            const float el = v ? __expf(lo - mxl) : 0.f;
            const float eh = v ? __expf(hi - mxh) : 0.f;
            sA[n] = pk2(el, eh);
            esl += el; esh += eh;
        }
        const ull sinvp = pk2(__fdividef(1.f, esl), __fdividef(1.f, esh));

        // ---- attn out + weighted sum ----
        ull xv = 0;
#pragma unroll
        for (int n = 0; n < N; n++) {
            const ull a = mul2(sA[n], sinvp);
            out_attn[gNDP + n * DP + gl] = a;
            xv = fma2(vp[n], a, xv);
        }

        // ---- stats finale ----
        const float cinv = __fdividef(1.f, (float)cnt);
        const ull meanp = mul2(ksum, dup2(cinv));
        const ull mabsp = mul2(kabs, dup2(cinv));
        const ull cm2 = mul2(mul2(meanp, meanp), dup2((float)cnt));
        ull varp = add2(ksq, cm2 ^ SGN2);
        const float rdc = __fdividef(1.f, fmaxf((float)(cnt - 1), 1.f));
        varp = mul2(varp, dup2(rdc));
        float vl, vh, mal, mah; up2(varp, vl, vh); up2(mabsp, mal, mah);
        float stl = 0.f, sth = 0.f, nsl = 0.f, nsh = 0.f;
        if (cnt > 1) {
            stl = sqrtf(fmaxf(vl, 0.f)); sth = sqrtf(fmaxf(vh, 0.f));
            nsl = stl / (mal + 1e-6f);   nsh = sth / (mah + 1e-6f);
        }

        // ---- x = xv @ oW + ob ----
        ((ull*)sX2[w])[hf * DP + gl] = xv;
        __syncwarp();
        ull xo = obp;
#pragma unroll
        for (int jx = 0; jx < 8; jx++) {
            const ulonglong2 x4 = sX2[w][hf * 8 + jx];
            float x0, x1, x2, x3; up2(x4.x, x0, x1); up2(x4.y, x2, x3);
            const ulonglong2 w01 = sOWP[2 * jx][gl];
            const ulonglong2 w23 = sOWP[2 * jx + 1][gl];
            xo = fma2(dup2(x0), w01.x, xo);
            xo = fma2(dup2(x1), w01.y, xo);
            xo = fma2(dup2(x2), w23.x, xo);
            xo = fma2(dup2(x3), w23.y, xo);
        }
        out_x[gDP + gl]    = xo;
        out_std[gDP + gl]  = pk2(stl, sth);
        out_nstd[gDP + gl] = pk2(nsl, nsh);
        __syncwarp();   // protect staging regions before next iteration
    }
}

extern "C" void kernel_launch(void* const* d_in, const int* in_sizes, int n_in,
                              void* d_out, int out_size)
{
    const float* q    = (const float*)d_in[0];
    const float* k    = (const float*)d_in[1];
    const float* pos  = (const float*)d_in[2];
    const int*   mask = (const int*)  d_in[3];
    const float* Wq   = (const float*)d_in[4];
    const float* Wk   = (const float*)d_in[5];
    const float* Wv   = (const float*)d_in[6];
    const float* pW1  = (const float*)d_in[7];
    const float* pb1  = (const float*)d_in[8];
    const float* pW2  = (const float*)d_in[9];
    const float* pb2  = (const float*)d_in[10];
    const float* aW1  = (const float*)d_in[11];
    const float* ab1  = (const float*)d_in[12];
    const float* aW2  = (const float*)d_in[13];
    const float* ab2  = (const float*)d_in[14];
    const float* oW   = (const float*)d_in[15];
    const float* ob   = (const float*)d_in[16];

    const int G = in_sizes[0] / D;

    float* base     = (float*)d_out;
    ull*   out_x    = (ull*)base;
    ull*   out_attn = (ull*)(base + (size_t)G * D);
    ull*   out_std  = (ull*)(base + (size_t)G * D + (size_t)G * N * D);
    ull*   out_nstd = (ull*)(base + 2 * (size_t)G * D + (size_t)G * N * D);

    const int threads = 256;
    const int blocks  = 304;
    attn2d_kernel<<<blocks, threads>>>(
        q, k, pos, mask, Wq, Wk, Wv,
        pW1, pb1, pW2, pb2, aW1, ab1, aW2, ab2, oW, ob,
        out_x, out_attn, out_std, out_nstd, G);
}

// round 8
// speedup vs baseline: 2.4671x; 1.0516x over previous
#include <cuda_runtime.h>
#include <math.h>

#define FULL 0xFFFFFFFFu
using ull = unsigned long long;

constexpr int D  = 32;
constexpr int N  = 10;
constexpr int H  = 4;
constexpr int DP = 16;   // dim-pairs; 16 lanes/group, 2 groups/warp

constexpr ull SGN2 = 0x8000000080000000ULL;
constexpr ull ABS2 = 0x7FFFFFFF7FFFFFFFULL;

__device__ __forceinline__ ull pk2(float lo, float hi) {
    ull r; asm("mov.b64 %0,{%1,%2};" : "=l"(r) : "f"(lo), "f"(hi)); return r;
}
__device__ __forceinline__ ull dup2(float v) {
    ull r; asm("mov.b64 %0,{%1,%1};" : "=l"(r) : "f"(v)); return r;
}
__device__ __forceinline__ void up2(ull p, float& lo, float& hi) {
    asm("mov.b64 {%0,%1},%2;" : "=f"(lo), "=f"(hi) : "l"(p));
}
__device__ __forceinline__ ull fma2(ull a, ull b, ull c) {
    ull r; asm("fma.rn.f32x2 %0,%1,%2,%3;" : "=l"(r) : "l"(a), "l"(b), "l"(c)); return r;
}
__device__ __forceinline__ ull add2(ull a, ull b) {
    ull r; asm("add.rn.f32x2 %0,%1,%2;" : "=l"(r) : "l"(a), "l"(b)); return r;
}
__device__ __forceinline__ ull mul2(ull a, ull b) {
    ull r; asm("mul.rn.f32x2 %0,%1,%2;" : "=l"(r) : "l"(a), "l"(b)); return r;
}
__device__ __forceinline__ void cpa16(unsigned s, const void* g) {
    asm volatile("cp.async.cg.shared.global [%0],[%1],16;" :: "r"(s), "l"(g));
}
#define CPA_COMMIT() asm volatile("cp.async.commit_group;" ::: "memory")
#define CPA_WAIT1()  asm volatile("cp.async.wait_group 1;" ::: "memory")

struct WB {
    ulonglong2 kbuf[2][160];  // k staging (double buffer); current buf reused as t
    ulonglong2 pbuf[2][20];   // pos
    ulonglong2 qbuf[2][16];   // q
    ulonglong2 hx2[40];       // h dup'd (80 ull) ; later xv dup'd (32 ull2)
    ulonglong2 yd2[40];       // y dup'd (80 ull)
};

__global__ void __launch_bounds__(128, 4) attn2d_kernel(
    const float* __restrict__ q,   const float* __restrict__ k,
    const float* __restrict__ pos, const int*   __restrict__ mask,
    const float* __restrict__ Wq,  const float* __restrict__ Wk,
    const float* __restrict__ Wv,
    const float* __restrict__ pW1, const float* __restrict__ pb1,
    const float* __restrict__ pW2, const float* __restrict__ pb2,
    const float* __restrict__ aW1, const float* __restrict__ ab1,
    const float* __restrict__ aW2, const float* __restrict__ ab2,
    const float* __restrict__ oW,  const float* __restrict__ ob,
    ull* __restrict__ out_x,  ull* __restrict__ out_attn,
    ull* __restrict__ out_std, ull* __restrict__ out_nstd,
    int G)
{
    __shared__ __align__(16) ulonglong2 sWqP[16][16];
    __shared__ __align__(16) ulonglong2 sWkP[16][16];
    __shared__ __align__(16) ulonglong2 sWvP[16][16];
    __shared__ __align__(16) ulonglong2 sOWP[16][16];
    __shared__ __align__(16) ulonglong2 sA1[4][8];
    __shared__ __align__(16) WB wbuf[4];

    const int tid = threadIdx.x;
    for (int i = tid; i < 256; i += 128) {   // weight staging (row-pair interleave)
        const int j2 = i >> 4, gl2 = (i & 15) * 2;
        ulonglong2 t;
        t.x = pk2(Wq[(2*j2)*D + gl2],   Wq[(2*j2)*D + gl2+1]);
        t.y = pk2(Wq[(2*j2+1)*D + gl2], Wq[(2*j2+1)*D + gl2+1]);
        sWqP[j2][i & 15] = t;
        t.x = pk2(Wk[(2*j2)*D + gl2],   Wk[(2*j2)*D + gl2+1]);
        t.y = pk2(Wk[(2*j2+1)*D + gl2], Wk[(2*j2+1)*D + gl2+1]);
        sWkP[j2][i & 15] = t;
        t.x = pk2(Wv[(2*j2)*D + gl2],   Wv[(2*j2)*D + gl2+1]);
        t.y = pk2(Wv[(2*j2+1)*D + gl2], Wv[(2*j2+1)*D + gl2+1]);
        sWvP[j2][i & 15] = t;
        t.x = pk2(oW[(2*j2)*D + gl2],   oW[(2*j2)*D + gl2+1]);
        t.y = pk2(oW[(2*j2+1)*D + gl2], oW[(2*j2+1)*D + gl2+1]);
        sOWP[j2][i & 15] = t;
    }
    if (tid < 32) {   // aW1 columns, dim-pair packed
        const int c = tid >> 3, jj = tid & 7;
        ulonglong2 t;
        t.x = pk2(aW1[(4*jj+0)*H + c], aW1[(4*jj+1)*H + c]);
        t.y = pk2(aW1[(4*jj+2)*H + c], aW1[(4*jj+3)*H + c]);
        sA1[c][jj] = t;
    }
    __syncthreads();

    const int lane = tid & 31, gl = lane & 15, hf = lane >> 4, w = tid >> 5;
    const int d2 = 2 * gl;
    const int cML = lane & 3;
    const float ab1c = ab1[cML], pb1c = pb1[cML];
    const float pw1c0 = pW1[0*H + cML], pw1c1 = pW1[1*H + cML];
    const float pw1c2 = pW1[2*H + cML], pw1c3 = pW1[3*H + cML];

    ull a2p[H], p2p[H];
#pragma unroll
    for (int c = 0; c < H; c++) {
        a2p[c] = pk2(aW2[c * D + d2], aW2[c * D + d2 + 1]);
        p2p[c] = pk2(pW2[c * D + d2], pW2[c * D + d2 + 1]);
    }
    const ull pb2p = pk2(pb2[d2], pb2[d2 + 1]);
    const ull ab2p = pk2(ab2[d2], ab2[d2 + 1]);
    const ull obp  = pk2(ob[d2],  ob[d2 + 1]);

    WB& wb = wbuf[w];
    ull* const hd = (ull*)wb.hx2;
    ull* const yd = (ull*)wb.yd2;

    const int warpsTotal = (gridDim.x * blockDim.x) >> 5;
    const int warpG = (blockIdx.x * blockDim.x + tid) >> 5;
    const int GP = G >> 1;

    auto prefetch = [&](int pp, int nb) {
        const ulonglong2* kf = (const ulonglong2*)k + (size_t)pp * 160;
        const unsigned kb = (unsigned)__cvta_generic_to_shared(&wb.kbuf[nb][lane]);
#pragma unroll
        for (int i = 0; i < 5; i++) cpa16(kb + i * 32 * 16, kf + i * 32 + lane);
        if (lane < 16)
            cpa16((unsigned)__cvta_generic_to_shared(&wb.qbuf[nb][lane]),
                  (const ulonglong2*)q + (size_t)pp * 16 + lane);
        if (lane < 20)
            cpa16((unsigned)__cvta_generic_to_shared(&wb.pbuf[nb][lane]),
                  (const ulonglong2*)pos + (size_t)pp * 20 + lane);
        CPA_COMMIT();
    };

    int mnext = 0;
    if (warpG < GP) {
        prefetch(warpG, 0);
        if (lane < 20) mnext = __ldg(mask + (size_t)warpG * 20 + lane);
    }

    int buf = 0;
    for (int p = warpG; p < GP; p += warpsTotal, buf ^= 1) {
        int pn = p + warpsTotal; if (pn >= GP) pn = GP - 1;
        prefetch(pn, buf ^ 1);
        const int mcur = mnext;
        if (lane < 20) mnext = __ldg(mask + (size_t)pn * 20 + lane);
        CPA_WAIT1();
        __syncwarp();

        const int g = 2 * p + hf;
        const size_t gDP  = (size_t)g * DP;
        const size_t gNDP = (size_t)g * (N * DP);

        const unsigned bal = __ballot_sync(FULL, (lane < 20) && (mcur != 0));
        unsigned vm = (bal >> (hf * 10)) & 0x3FFu;
        int cnt = __popc(vm);
        if (cnt == 0) { vm = 0x3FFu; cnt = N; }

        // ---- qp = q @ Wq ----
        ull qp = 0;
#pragma unroll
        for (int jq = 0; jq < 8; jq++) {
            const ulonglong2 q4 = wb.qbuf[buf][hf * 8 + jq];
            float q0, q1, q2, q3; up2(q4.x, q0, q1); up2(q4.y, q2, q3);
            const ulonglong2 w01 = sWqP[2 * jq][gl];
            const ulonglong2 w23 = sWqP[2 * jq + 1][gl];
            qp = fma2(dup2(q0), w01.x, qp);
            qp = fma2(dup2(q1), w01.y, qp);
            qp = fma2(dup2(q2), w23.x, qp);
            qp = fma2(dup2(q3), w23.y, qp);
        }
        const ull nqp = qp ^ SGN2;

        // ---- h-tasks: 80 scalar hidden units of the pos MLP, dedup'd ----
#pragma unroll
        for (int r = 0; r < 3; r++) {
            if (r < 2 || lane < 16) {
                const int t_id = r * 32 + lane;
                const int row = t_id >> 2;
                const ulonglong2 pp = wb.pbuf[buf][row];
                float px, py, pz, pw; up2(pp.x, px, py); up2(pp.y, pz, pw);
                float ph = pb1c;
                ph = fmaf(px, pw1c0, ph);
                ph = fmaf(py, pw1c1, ph);
                ph = fmaf(pz, pw1c2, ph);
                ph = fmaf(pw, pw1c3, ph);
                hd[t_id] = dup2(fmaxf(ph, 0.f));
            }
        }

        // ---- kp/vp projections ----
        ull kp[N], vp[N];
#pragma unroll
        for (int n = 0; n < N; n++) { kp[n] = 0; vp[n] = 0; }
#pragma unroll
        for (int j4 = 0; j4 < 8; j4++) {
            const ulonglong2 wk01 = sWkP[2 * j4][gl];
            const ulonglong2 wk23 = sWkP[2 * j4 + 1][gl];
            const ulonglong2 wv01 = sWvP[2 * j4][gl];
            const ulonglong2 wv23 = sWvP[2 * j4 + 1][gl];
#pragma unroll
            for (int n = 0; n < N; n++) {
                const ulonglong2 kk = wb.kbuf[buf][hf * 80 + n * 8 + j4];
                float k0, k1, k2, k3; up2(kk.x, k0, k1); up2(kk.y, k2, k3);
                const ull d0 = dup2(k0), d1 = dup2(k1), d2d = dup2(k2), d3 = dup2(k3);
                kp[n] = fma2(d0, wk01.x, kp[n]);
                kp[n] = fma2(d1, wk01.y, kp[n]);
                kp[n] = fma2(d2d, wk23.x, kp[n]);
                kp[n] = fma2(d3, wk23.y, kp[n]);
                vp[n] = fma2(d0, wv01.x, vp[n]);
                vp[n] = fma2(d1, wv01.y, vp[n]);
                vp[n] = fma2(d2d, wv23.x, vp[n]);
                vp[n] = fma2(d3, wv23.y, vp[n]);
            }
        }
        __syncwarp();   // k reads & h writes complete

        // ---- t-phase: pe from dup'd h; t -> smem (overlays k buf); stats ----
        ull* const tS = (ull*)wb.kbuf[buf];
        const ulonglong2* hd2 = (const ulonglong2*)hd;
        ull ksum = 0, kabs = 0, ksq = 0;
#pragma unroll
        for (int n = 0; n < N; n++) {
            const int row = hf * 10 + n;
            const ulonglong2 h01 = hd2[row * 2];
            const ulonglong2 h23 = hd2[row * 2 + 1];
            ull pe = pb2p;
            pe = fma2(h01.x, p2p[0], pe);
            pe = fma2(h01.y, p2p[1], pe);
            pe = fma2(h23.x, p2p[2], pe);
            pe = fma2(h23.y, p2p[3], pe);
            vp[n] = add2(vp[n], pe);
            tS[row * 16 + (gl ^ ((row & 7) << 1))] = add2(add2(kp[n], nqp), pe);
            const float mk = ((vm >> n) & 1u) ? 1.f : 0.f;
            const ull md = dup2(mk);
            const ull kpm = mul2(kp[n], md);
            ksum = add2(ksum, kpm);
            kabs = add2(kabs, kpm & ABS2);
            ksq  = fma2(kpm, kp[n], ksq);
        }
        __syncwarp();

        // ---- dot tasks: y = relu(t . aW1[:,c] + ab1[c]), stored dup'd ----
        {
            const ulonglong2* sT2 = (const ulonglong2*)tS;
#pragma unroll
            for (int r = 0; r < 3; r++) {
                if (r < 2 || lane < 16) {
                    const int t_id = r * 32 + lane;
                    const int row = t_id >> 2;
                    const int sw = row & 7;
                    ull acc = 0;
#pragma unroll
                    for (int jj = 0; jj < 8; jj++) {
                        const ulonglong2 tt = sT2[row * 8 + (jj ^ sw)];
                        const ulonglong2 ww = sA1[cML][jj];
                        acc = fma2(tt.x, ww.x, acc);
                        acc = fma2(tt.y, ww.y, acc);
                    }
                    float lo, hi; up2(acc, lo, hi);
                    yd[t_id] = dup2(fmaxf(lo + hi + ab1c, 0.f));
                }
            }
        }
        __syncwarp();

        // ---- scores from dup'd y; masked softmax over n ----
        const ulonglong2* yd2c = (const ulonglong2*)yd;
        ull sA[N];
#pragma unroll
        for (int n = 0; n < N; n++) {
            const int row = hf * 10 + n;
            const ulonglong2 y01 = yd2c[row * 2];
            const ulonglong2 y23 = yd2c[row * 2 + 1];
            ull s = ab2p;
            s = fma2(y01.x, a2p[0], s);
            s = fma2(y01.y, a2p[1], s);
            s = fma2(y23.x, a2p[2], s);
            s = fma2(y23.y, a2p[3], s);
            sA[n] = s;
        }
        float mxl = -3e38f, mxh = -3e38f;
#pragma unroll
        for (int n = 0; n < N; n++) {
            float lo, hi; up2(sA[n], lo, hi);
            if ((vm >> n) & 1u) { mxl = fmaxf(mxl, lo); mxh = fmaxf(mxh, hi); }
        }
        float esl = 0.f, esh = 0.f;
#pragma unroll
        for (int n = 0; n < N; n++) {
            float lo, hi; up2(sA[n], lo, hi);
            const bool v = (vm >> n) & 1u;
            const float el = v ? __expf(lo - mxl) : 0.f;
            const float eh = v ? __expf(hi - mxh) : 0.f;
            sA[n] = pk2(el, eh);
            esl += el; esh += eh;
        }
        const ull sinvp = pk2(__fdividef(1.f, esl), __fdividef(1.f, esh));

        // ---- attn out + weighted sum ----
        ull xv = 0;
#pragma unroll
        for (int n = 0; n < N; n++) {
            const ull a = mul2(sA[n], sinvp);
            out_attn[gNDP + n * DP + gl] = a;
            xv = fma2(vp[n], a, xv);
        }

        // ---- stats finale ----
        const float cinv = __fdividef(1.f, (float)cnt);
        const ull meanp = mul2(ksum, dup2(cinv));
        const ull mabsp = mul2(kabs, dup2(cinv));
        const ull cm2 = mul2(mul2(meanp, meanp), dup2((float)cnt));
        ull varp = add2(ksq, cm2 ^ SGN2);
        const float rdc = __fdividef(1.f, fmaxf((float)(cnt - 1), 1.f));
        varp = mul2(varp, dup2(rdc));
        float vl, vh, mal, mah; up2(varp, vl, vh); up2(mabsp, mal, mah);
        float stl = 0.f, sth = 0.f, nsl = 0.f, nsh = 0.f;
        if (cnt > 1) {
            stl = sqrtf(fmaxf(vl, 0.f)); sth = sqrtf(fmaxf(vh, 0.f));
            nsl = stl / (mal + 1e-6f);   nsh = sth / (mah + 1e-6f);
        }

        // ---- x = xv @ oW + ob (xv stored dup'd, h region dead) ----
        {
            float xl, xh; up2(xv, xl, xh);
            ulonglong2 t; t.x = dup2(xl); t.y = dup2(xh);
            wb.hx2[hf * 16 + gl] = t;
        }
        __syncwarp();
        ull xo = obp;
#pragma unroll
        for (int jx = 0; jx < 8; jx++) {
            const ulonglong2 x01 = wb.hx2[hf * 16 + 2 * jx];
            const ulonglong2 x23 = wb.hx2[hf * 16 + 2 * jx + 1];
            const ulonglong2 w01 = sOWP[2 * jx][gl];
            const ulonglong2 w23 = sOWP[2 * jx + 1][gl];
            xo = fma2(x01.x, w01.x, xo);
            xo = fma2(x01.y, w01.y, xo);
            xo = fma2(x23.x, w23.x, xo);
            xo = fma2(x23.y, w23.y, xo);
        }
        out_x[gDP + gl]    = xo;
        out_std[gDP + gl]  = pk2(stl, sth);
        out_nstd[gDP + gl] = pk2(nsl, nsh);
        __syncwarp();   // protect reused regions before next iteration
    }
}

extern "C" void kernel_launch(void* const* d_in, const int* in_sizes, int n_in,
                              void* d_out, int out_size)
{
    const float* q    = (const float*)d_in[0];
    const float* k    = (const float*)d_in[1];
    const float* pos  = (const float*)d_in[2];
    const int*   mask = (const int*)  d_in[3];
    const float* Wq   = (const float*)d_in[4];
    const float* Wk   = (const float*)d_in[5];
    const float* Wv   = (const float*)d_in[6];
    const float* pW1  = (const float*)d_in[7];
    const float* pb1  = (const float*)d_in[8];
    const float* pW2  = (const float*)d_in[9];
    const float* pb2  = (const float*)d_in[10];
    const float* aW1  = (const float*)d_in[11];
    const float* ab1  = (const float*)d_in[12];
    const float* aW2  = (const float*)d_in[13];
    const float* ab2  = (const float*)d_in[14];
    const float* oW   = (const float*)d_in[15];
    const float* ob   = (const float*)d_in[16];

    const int G = in_sizes[0] / D;

    float* base     = (float*)d_out;
    ull*   out_x    = (ull*)base;
    ull*   out_attn = (ull*)(base + (size_t)G * D);
    ull*   out_std  = (ull*)(base + (size_t)G * D + (size_t)G * N * D);
    ull*   out_nstd = (ull*)(base + 2 * (size_t)G * D + (size_t)G * N * D);

    const int threads = 128;
    const int blocks  = 608;   // 4 blocks/SM persistent on 152 SMs
    attn2d_kernel<<<blocks, threads>>>(
        q, k, pos, mask, Wq, Wk, Wv,
        pW1, pb1, pW2, pb2, aW1, ab1, aW2, ab2, oW, ob,
        out_x, out_attn, out_std, out_nstd, G);
}

// round 9
// speedup vs baseline: 2.5155x; 1.0197x over previous
#include <cuda_runtime.h>
#include <math.h>

#define FULL 0xFFFFFFFFu
using ull = unsigned long long;

constexpr int D  = 32;
constexpr int N  = 10;
constexpr int H  = 4;
constexpr int DP = 16;   // dim-pairs; 16 lanes/group, 2 groups/warp

constexpr ull SGN2 = 0x8000000080000000ULL;
constexpr ull ABS2 = 0x7FFFFFFF7FFFFFFFULL;

__device__ __forceinline__ ull pk2(float lo, float hi) {
    ull r; asm("mov.b64 %0,{%1,%2};" : "=l"(r) : "f"(lo), "f"(hi)); return r;
}
__device__ __forceinline__ ull dup2(float v) {
    ull r; asm("mov.b64 %0,{%1,%1};" : "=l"(r) : "f"(v)); return r;
}
__device__ __forceinline__ void up2(ull p, float& lo, float& hi) {
    asm("mov.b64 {%0,%1},%2;" : "=f"(lo), "=f"(hi) : "l"(p));
}
__device__ __forceinline__ ull fma2(ull a, ull b, ull c) {
    ull r; asm("fma.rn.f32x2 %0,%1,%2,%3;" : "=l"(r) : "l"(a), "l"(b), "l"(c)); return r;
}
__device__ __forceinline__ ull add2(ull a, ull b) {
    ull r; asm("add.rn.f32x2 %0,%1,%2;" : "=l"(r) : "l"(a), "l"(b)); return r;
}
__device__ __forceinline__ ull mul2(ull a, ull b) {
    ull r; asm("mul.rn.f32x2 %0,%1,%2;" : "=l"(r) : "l"(a), "l"(b)); return r;
}
__device__ __forceinline__ void cpa16(unsigned s, const void* g) {
    asm volatile("cp.async.cg.shared.global [%0],[%1],16;" :: "r"(s), "l"(g));
}
#define CPA_COMMIT() asm volatile("cp.async.commit_group;" ::: "memory")
#define CPA_WAIT1()  asm volatile("cp.async.wait_group 1;" ::: "memory")

struct WB {
    ulonglong2 kbuf[2][160];  // k staging, PRE-SWIZZLED; cur buf reused for xv-dup
    ulonglong2 pbuf[2][20];   // pos
    ulonglong2 qbuf[2][16];   // q
    float ph[80];             // relu'd pos-MLP hidden units (row*4+c)
    float yv[80];             // relu'd score-MLP hidden units (row*4+c)
    float uq[8];              // per-group c-constants: ab1+cb-q.Fq
};

__global__ void __launch_bounds__(128, 4) attn2d_kernel(
    const float* __restrict__ q,   const float* __restrict__ k,
    const float* __restrict__ pos, const int*   __restrict__ mask,
    const float* __restrict__ Wq,  const float* __restrict__ Wk,
    const float* __restrict__ Wv,
    const float* __restrict__ pW1, const float* __restrict__ pb1,
    const float* __restrict__ pW2, const float* __restrict__ pb2,
    const float* __restrict__ aW1, const float* __restrict__ ab1,
    const float* __restrict__ aW2, const float* __restrict__ ab2,
    const float* __restrict__ oW,  const float* __restrict__ ob,
    ull* __restrict__ out_x,  ull* __restrict__ out_attn,
    ull* __restrict__ out_std, ull* __restrict__ out_nstd,
    int G)
{
    __shared__ __align__(16) ulonglong2 sWkP[16][16];
    __shared__ __align__(16) ulonglong2 sWvP[16][16];
    __shared__ __align__(16) ulonglong2 sOWP[16][16];
    __shared__ __align__(16) ulonglong2 sFk[4][9];   // Wk@aW1 col c packed, stride-9 pad
    __shared__ __align__(16) ulonglong2 sFq[4][9];   // Wq@aW1 col c packed
    __shared__ __align__(16) float sM[4][4];         // sM[c][h] = (pW2@aW1)[h][c]
    __shared__ float sCB[4];                         // ab1[c] + pb2.aW1[:,c]
    __shared__ __align__(16) WB wbuf[4];

    const int tid = threadIdx.x;
    // ---- phase 0: fused-weight raw compute (into temp) + big-weight staging ----
    float* tmpF = (float*)wbuf[0].kbuf;   // 256 floats temp: Fk then Fq, idx j*4+c
    {
        const int j = tid >> 2, c = tid & 3;   // tid < 128 always
        float fk = 0.f, fq = 0.f;
        for (int d = 0; d < D; d++) {
            const float a = aW1[d * H + c];
            fk = fmaf(Wk[j * D + d], a, fk);
            fq = fmaf(Wq[j * D + d], a, fq);
        }
        tmpF[tid] = fk; tmpF[128 + tid] = fq;
    }
    for (int i = tid; i < 256; i += 128) {   // row-pair interleaved weights
        const int j2 = i >> 4, gl2 = (i & 15) * 2;
        ulonglong2 t;
        t.x = pk2(Wk[(2*j2)*D + gl2],   Wk[(2*j2)*D + gl2+1]);
        t.y = pk2(Wk[(2*j2+1)*D + gl2], Wk[(2*j2+1)*D + gl2+1]);
        sWkP[j2][i & 15] = t;
        t.x = pk2(Wv[(2*j2)*D + gl2],   Wv[(2*j2)*D + gl2+1]);
        t.y = pk2(Wv[(2*j2+1)*D + gl2], Wv[(2*j2+1)*D + gl2+1]);
        sWvP[j2][i & 15] = t;
        t.x = pk2(oW[(2*j2)*D + gl2],   oW[(2*j2)*D + gl2+1]);
        t.y = pk2(oW[(2*j2+1)*D + gl2], oW[(2*j2+1)*D + gl2+1]);
        sOWP[j2][i & 15] = t;
    }
    if (tid < 16) {
        const int h = tid >> 2, c = tid & 3;
        float m = 0.f;
        for (int d = 0; d < D; d++) m = fmaf(pW2[h * D + d], aW1[d * H + c], m);
        sM[c][h] = m;
    }
    if (tid < 4) {
        float cb = ab1[tid];
        for (int d = 0; d < D; d++) cb = fmaf(pb2[d], aW1[d * H + tid], cb);
        sCB[tid] = cb;
    }
    __syncthreads();
    if (tid < 32) {   // repack fused weights by column, dim-pair packed
        const int c = tid >> 3, jj = tid & 7;
        ulonglong2 t;
        t.x = pk2(tmpF[(4*jj+0)*4 + c], tmpF[(4*jj+1)*4 + c]);
        t.y = pk2(tmpF[(4*jj+2)*4 + c], tmpF[(4*jj+3)*4 + c]);
        sFk[c][jj] = t;
        t.x = pk2(tmpF[128 + (4*jj+0)*4 + c], tmpF[128 + (4*jj+1)*4 + c]);
        t.y = pk2(tmpF[128 + (4*jj+2)*4 + c], tmpF[128 + (4*jj+3)*4 + c]);
        sFq[c][jj] = t;
    }
    __syncthreads();   // tmpF dead; wbuf usable

    const int lane = tid & 31, gl = lane & 15, hf = lane >> 4, w = tid >> 5;
    const int d2 = 2 * gl;
    const int cML = lane & 3;
    const float pb1c = pb1[cML];
    const float pw1c0 = pW1[0*H + cML], pw1c1 = pW1[1*H + cML];
    const float pw1c2 = pW1[2*H + cML], pw1c3 = pW1[3*H + cML];

    ull a2p[H], p2p[H];
#pragma unroll
    for (int c = 0; c < H; c++) {
        a2p[c] = pk2(aW2[c * D + d2], aW2[c * D + d2 + 1]);
        p2p[c] = pk2(pW2[c * D + d2], pW2[c * D + d2 + 1]);
    }
    const ull pb2p = pk2(pb2[d2], pb2[d2 + 1]);
    const ull ab2p = pk2(ab2[d2], ab2[d2 + 1]);
    const ull obp  = pk2(ob[d2],  ob[d2 + 1]);

    WB& wb = wbuf[w];
    const int warpsTotal = (gridDim.x * blockDim.x) >> 5;
    const int warpG = (blockIdx.x * blockDim.x + tid) >> 5;
    const int GP = G >> 1;

    auto prefetch = [&](int pp, int nb) {
        const ulonglong2* kf = (const ulonglong2*)k + (size_t)pp * 160;
        ulonglong2* kb = wb.kbuf[nb];
#pragma unroll
        for (int i = 0; i < 5; i++) {
            const int flat = i * 32 + lane;
            const int row = flat >> 3, j4 = flat & 7;
            cpa16((unsigned)__cvta_generic_to_shared(kb + row * 8 + (j4 ^ (row & 7))),
                  kf + flat);
        }
        if (lane < 16)
            cpa16((unsigned)__cvta_generic_to_shared(&wb.qbuf[nb][lane]),
                  (const ulonglong2*)q + (size_t)pp * 16 + lane);
        if (lane < 20)
            cpa16((unsigned)__cvta_generic_to_shared(&wb.pbuf[nb][lane]),
                  (const ulonglong2*)pos + (size_t)pp * 20 + lane);
        CPA_COMMIT();
    };

    int mnext = 0;
    if (warpG < GP) {
        prefetch(warpG, 0);
        if (lane < 20) mnext = __ldg(mask + (size_t)warpG * 20 + lane);
    }

    int buf = 0;
    for (int p = warpG; p < GP; p += warpsTotal, buf ^= 1) {
        int pn = p + warpsTotal; if (pn >= GP) pn = GP - 1;
        prefetch(pn, buf ^ 1);
        const int mcur = mnext;
        if (lane < 20) mnext = __ldg(mask + (size_t)pn * 20 + lane);
        CPA_WAIT1();
        __syncwarp();

        const int g = 2 * p + hf;
        const size_t gDP  = (size_t)g * DP;
        const size_t gNDP = (size_t)g * (N * DP);

        const unsigned bal = __ballot_sync(FULL, (lane < 20) && (mcur != 0));
        unsigned vm = (bal >> (hf * 10)) & 0x3FFu;
        int cnt = __popc(vm);
        if (cnt == 0) { vm = 0x3FFu; cnt = N; }

        // ---- h-tasks (80 hidden units, dedup'd) + uq-tasks (8 per-group consts) ----
#pragma unroll
        for (int r = 0; r < 3; r++) {
            if (r < 2 || lane < 16) {
                const int t_id = r * 32 + lane;
                const int row = t_id >> 2;
                const ulonglong2 pp = wb.pbuf[buf][row];
                float px, py, pz, pw; up2(pp.x, px, py); up2(pp.y, pz, pw);
                float ph = pb1c;
                ph = fmaf(px, pw1c0, ph);
                ph = fmaf(py, pw1c1, ph);
                ph = fmaf(pz, pw1c2, ph);
                ph = fmaf(pw, pw1c3, ph);
                wb.ph[t_id] = fmaxf(ph, 0.f);
            }
        }
        if (lane >= 16 && lane < 24) {   // uq: grp = (lane-16)>>2, c = lane&3
            const int u = lane - 16, grp = u >> 2;
            ull acc = 0;
#pragma unroll
            for (int jj = 0; jj < 8; jj++) {
                const ulonglong2 q4 = wb.qbuf[buf][grp * 8 + jj];
                const ulonglong2 f4 = sFq[cML][jj];
                acc = fma2(q4.x, f4.x, acc);
                acc = fma2(q4.y, f4.y, acc);
            }
            float lo, hi; up2(acc, lo, hi);
            wb.uq[u] = sCB[cML] - (lo + hi);
        }
        __syncwarp();

        // ---- y-tasks: y = relu(k.Fk[:,c] + uq + ph.M[:,c]) on RAW k ----
        {
            const ulonglong2* kb = wb.kbuf[buf];
#pragma unroll
            for (int r = 0; r < 3; r++) {
                if (r < 2 || lane < 16) {
                    const int t_id = r * 32 + lane;
                    const int row = t_id >> 2;
                    const int sw = row & 7;
                    ull acc = 0;
#pragma unroll
                    for (int jj = 0; jj < 8; jj++) {
                        const ulonglong2 kk = kb[row * 8 + (jj ^ sw)];
                        const ulonglong2 ff = sFk[cML][jj];
                        acc = fma2(kk.x, ff.x, acc);
                        acc = fma2(kk.y, ff.y, acc);
                    }
                    float lo, hi; up2(acc, lo, hi);
                    float s = lo + hi + wb.uq[(row >= 10 ? 4 : 0) + cML];
                    const float4 p4 = *(const float4*)&wb.ph[row * 4];
                    const float4 m4 = *(const float4*)&sM[cML][0];
                    s = fmaf(p4.x, m4.x, s);
                    s = fmaf(p4.y, m4.y, s);
                    s = fmaf(p4.z, m4.z, s);
                    s = fmaf(p4.w, m4.w, s);
                    wb.yv[t_id] = fmaxf(s, 0.f);
                }
            }
        }

        // ---- kp/vp projections (needed for stats + output) ----
        ull kp[N], vp[N];
#pragma unroll
        for (int n = 0; n < N; n++) { kp[n] = 0; vp[n] = 0; }
#pragma unroll
        for (int j4 = 0; j4 < 8; j4++) {
            const ulonglong2 wk01 = sWkP[2 * j4][gl];
            const ulonglong2 wk23 = sWkP[2 * j4 + 1][gl];
            const ulonglong2 wv01 = sWvP[2 * j4][gl];
            const ulonglong2 wv23 = sWvP[2 * j4 + 1][gl];
#pragma unroll
            for (int n = 0; n < N; n++) {
                const int row = hf * 10 + n;
                const ulonglong2 kk = wb.kbuf[buf][row * 8 + (j4 ^ (row & 7))];
                float k0, k1, k2, k3; up2(kk.x, k0, k1); up2(kk.y, k2, k3);
                const ull d0 = dup2(k0), d1 = dup2(k1), d2d = dup2(k2), d3 = dup2(k3);
                kp[n] = fma2(d0, wk01.x, kp[n]);
                kp[n] = fma2(d1, wk01.y, kp[n]);
                kp[n] = fma2(d2d, wk23.x, kp[n]);
                kp[n] = fma2(d3, wk23.y, kp[n]);
                vp[n] = fma2(d0, wv01.x, vp[n]);
                vp[n] = fma2(d1, wv01.y, vp[n]);
                vp[n] = fma2(d2d, wv23.x, vp[n]);
                vp[n] = fma2(d3, wv23.y, vp[n]);
            }
        }
        __syncwarp();   // y-task writes visible; kbuf reads complete

        // ---- epilogue per n: stats, pe->vp, scores ----
        ull ksum = 0, kabs = 0, ksq = 0, sA[N];
#pragma unroll
        for (int n = 0; n < N; n++) {
            const int row = hf * 10 + n;
            const float mk = ((vm >> n) & 1u) ? 1.f : 0.f;
            const ull md = dup2(mk);
            const ull kpm = mul2(kp[n], md);
            ksum = add2(ksum, kpm);
            kabs = add2(kabs, kpm & ABS2);
            ksq  = fma2(kpm, kp[n], ksq);

            const float4 p4 = *(const float4*)&wb.ph[row * 4];
            ull pe = pb2p;
            pe = fma2(dup2(p4.x), p2p[0], pe);
            pe = fma2(dup2(p4.y), p2p[1], pe);
            pe = fma2(dup2(p4.z), p2p[2], pe);
            pe = fma2(dup2(p4.w), p2p[3], pe);
            vp[n] = add2(vp[n], pe);

            const float4 y4 = *(const float4*)&wb.yv[row * 4];
            ull s = ab2p;
            s = fma2(dup2(y4.x), a2p[0], s);
            s = fma2(dup2(y4.y), a2p[1], s);
            s = fma2(dup2(y4.z), a2p[2], s);
            s = fma2(dup2(y4.w), a2p[3], s);
            sA[n] = s;
        }

        // ---- masked softmax over n ----
        float mxl = -3e38f, mxh = -3e38f;
#pragma unroll
        for (int n = 0; n < N; n++) {
            float lo, hi; up2(sA[n], lo, hi);
            if ((vm >> n) & 1u) { mxl = fmaxf(mxl, lo); mxh = fmaxf(mxh, hi); }
        }
        float esl = 0.f, esh = 0.f;
#pragma unroll
        for (int n = 0; n < N; n++) {
            float lo, hi; up2(sA[n], lo, hi);
            const bool v = (vm >> n) & 1u;
            const float el = v ? __expf(lo - mxl) : 0.f;
            const float eh = v ? __expf(hi - mxh) : 0.f;
            sA[n] = pk2(el, eh);
            esl += el; esh += eh;
        }
        const ull sinvp = pk2(__fdividef(1.f, esl), __fdividef(1.f, esh));

        // ---- attn out + weighted sum ----
        ull xv = 0;
#pragma unroll
        for (int n = 0; n < N; n++) {
            const ull a = mul2(sA[n], sinvp);
            out_attn[gNDP + n * DP + gl] = a;
            xv = fma2(vp[n], a, xv);
        }

        // ---- stats finale ----
        const float cinv = __fdividef(1.f, (float)cnt);
        const ull meanp = mul2(ksum, dup2(cinv));
        const ull mabsp = mul2(kabs, dup2(cinv));
        const ull cm2 = mul2(mul2(meanp, meanp), dup2((float)cnt));
        ull varp = add2(ksq, cm2 ^ SGN2);
        const float rdc = __fdividef(1.f, fmaxf((float)(cnt - 1), 1.f));
        varp = mul2(varp, dup2(rdc));
        float vl, vh, mal, mah; up2(varp, vl, vh); up2(mabsp, mal, mah);
        float stl = 0.f, sth = 0.f, nsl = 0.f, nsh = 0.f;
        if (cnt > 1) {
            stl = sqrtf(fmaxf(vl, 0.f)); sth = sqrtf(fmaxf(vh, 0.f));
            nsl = stl / (mal + 1e-6f);   nsh = sth / (mah + 1e-6f);
        }

        // ---- x = xv @ oW + ob (dup'd xv in dead kbuf[buf]) ----
        {
            ulonglong2* xd = wb.kbuf[buf];
            float xl, xh; up2(xv, xl, xh);
            ulonglong2 t; t.x = dup2(xl); t.y = dup2(xh);
            xd[hf * 16 + gl] = t;
        }
        __syncwarp();
        ull xo = obp;
#pragma unroll
        for (int jx = 0; jx < 8; jx++) {
            const ulonglong2 x01 = wb.kbuf[buf][hf * 16 + 2 * jx];
            const ulonglong2 x23 = wb.kbuf[buf][hf * 16 + 2 * jx + 1];
            const ulonglong2 w01 = sOWP[2 * jx][gl];
            const ulonglong2 w23 = sOWP[2 * jx + 1][gl];
            xo = fma2(x01.x, w01.x, xo);
            xo = fma2(x01.y, w01.y, xo);
            xo = fma2(x23.x, w23.x, xo);
            xo = fma2(x23.y, w23.y, xo);
        }
        out_x[gDP + gl]    = xo;
        out_std[gDP + gl]  = pk2(stl, sth);
        out_nstd[gDP + gl] = pk2(nsl, nsh);
        __syncwarp();   // protect reused regions before next iteration
    }
}

extern "C" void kernel_launch(void* const* d_in, const int* in_sizes, int n_in,
                              void* d_out, int out_size)
{
    const float* q    = (const float*)d_in[0];
    const float* k    = (const float*)d_in[1];
    const float* pos  = (const float*)d_in[2];
    const int*   mask = (const int*)  d_in[3];
    const float* Wq   = (const float*)d_in[4];
    const float* Wk   = (const float*)d_in[5];
    const float* Wv   = (const float*)d_in[6];
    const float* pW1  = (const float*)d_in[7];
    const float* pb1  = (const float*)d_in[8];
    const float* pW2  = (const float*)d_in[9];
    const float* pb2  = (const float*)d_in[10];
    const float* aW1  = (const float*)d_in[11];
    const float* ab1  = (const float*)d_in[12];
    const float* aW2  = (const float*)d_in[13];
    const float* ab2  = (const float*)d_in[14];
    const float* oW   = (const float*)d_in[15];
    const float* ob   = (const float*)d_in[16];

    const int G = in_sizes[0] / D;

    float* base     = (float*)d_out;
    ull*   out_x    = (ull*)base;
    ull*   out_attn = (ull*)(base + (size_t)G * D);
    ull*   out_std  = (ull*)(base + (size_t)G * D + (size_t)G * N * D);
    ull*   out_nstd = (ull*)(base + 2 * (size_t)G * D + (size_t)G * N * D);

    const int threads = 128;
    const int blocks  = 608;   // 4 blocks/SM persistent on 152 SMs
    attn2d_kernel<<<blocks, threads>>>(
        q, k, pos, mask, Wq, Wk, Wv,
        pW1, pb1, pW2, pb2, aW1, ab1, aW2, ab2, oW, ob,
        out_x, out_attn, out_std, out_nstd, G);
}